// round 1
// baseline (speedup 1.0000x reference)
#include <cuda_runtime.h>

// EarthMoverDistance: entropic Sinkhorn OT, B=8, N=2048, D=3, eps=0.005, 50 iters.
//
// Formulation trick: store packed point+dual arrays
//   A[i] = (x0, x1, x2,  f_i - |x_i|^2)          (raw coords)
//   B[j] = (2*y0, 2*y1, 2*y2,  g_j - |y_j|^2)    (coords pre-scaled by 2)
// Then for the f-update row i:
//   v_ij = g_j - C_ij = Bw_j + dot(x_i, 2*y_j) - |x_i|^2
// and the -|x_i|^2 term cancels out of the dual update entirely:
//   Aw_i_new = eps*log_mu - max_j(Bw_j + dot') - eps*ln(sum_j exp((t - max)/eps))
// The g-update is exactly symmetric (the single factor of 2 lives on the B side
// so dot' = 2*dot in both directions). For the final plan,
//   (f_i + g_j - C_ij)/eps = (Aw_i + Bw_j + dot')/eps   (norms cancel again).

#define NB      8
#define NP      2048
#define NTOT    (NB * NP)
#define ITERS   50
#define EPS     0.005f
#define LN2     0.69314718055994531f
// C2 = log2(e)/eps
#define C2      288.53900817779268f
// EPSLOGMU = -eps * ln(2048)
#define EPSLOGMU (-0.038123094930796995f)
#define NBLK    (NP / 32)           // 64 row-blocks per batch
#define NPART   (NBLK * NB)         // 512 partials

__device__ float4 g_A[NTOT];
__device__ float4 g_B[NTOT];
__device__ float  g_part[NPART];

__device__ __forceinline__ float ex2f(float x) {
    float r; asm("ex2.approx.ftz.f32 %0, %1;" : "=f"(r) : "f"(x)); return r;
}
__device__ __forceinline__ float lg2f(float x) {
    float r; asm("lg2.approx.f32 %0, %1;" : "=f"(r) : "f"(x)); return r;
}

// ---------------------------------------------------------------------------
// Init: build packed arrays. f0 = g0 = 0.
// ---------------------------------------------------------------------------
__global__ __launch_bounds__(256) void init_kernel(const float* __restrict__ p1,
                                                   const float* __restrict__ p2) {
    int idx = blockIdx.x * blockDim.x + threadIdx.x;
    if (idx < NTOT) {
        float x0 = p1[idx * 3 + 0], x1 = p1[idx * 3 + 1], x2 = p1[idx * 3 + 2];
        g_A[idx] = make_float4(x0, x1, x2, -(x0 * x0 + x1 * x1 + x2 * x2));
    } else if (idx < 2 * NTOT) {
        int k = idx - NTOT;
        float y0 = p2[k * 3 + 0], y1 = p2[k * 3 + 1], y2 = p2[k * 3 + 2];
        g_B[k] = make_float4(2.f * y0, 2.f * y1, 2.f * y2,
                             -(y0 * y0 + y1 * y1 + y2 * y2));
    }
}

// ---------------------------------------------------------------------------
// One Sinkhorn half-step. DIR==0: update A (f) from B; DIR==1: update B from A.
// Warp handles 4 consecutive rows of dst; lanes stride the j dimension.
// Two-pass max-shifted logsumexp; 3-FMA dot per pair; stream load reused 4x.
// ---------------------------------------------------------------------------
template <int DIR>
__global__ __launch_bounds__(256) void sink_kernel() {
    const float4* __restrict__ src = (DIR == 0) ? g_B : g_A;
    float4*                    dst = (DIR == 0) ? g_A : g_B;

    int lane = threadIdx.x & 31;
    int warp = threadIdx.x >> 5;
    int b    = blockIdx.y;
    int row0 = blockIdx.x * 32 + warp * 4;

    const float4* S = src + b * NP;
    float4*       D = dst + b * NP + row0;

    float rx[4], ry[4], rz[4];
#pragma unroll
    for (int r = 0; r < 4; r++) {
        float4 t = D[r];
        rx[r] = t.x; ry[r] = t.y; rz[r] = t.z;
    }

    // ---- pass 1: per-row max of (Sw_j + dot') ----
    float m[4];
#pragma unroll
    for (int r = 0; r < 4; r++) m[r] = -1e30f;

#pragma unroll 2
    for (int j = lane; j < NP; j += 32) {
        float4 p = S[j];
#pragma unroll
        for (int r = 0; r < 4; r++) {
            float t = fmaf(rx[r], p.x, p.w);
            t = fmaf(ry[r], p.y, t);
            t = fmaf(rz[r], p.z, t);
            m[r] = fmaxf(m[r], t);
        }
    }
#pragma unroll
    for (int r = 0; r < 4; r++) {
#pragma unroll
        for (int o = 16; o; o >>= 1)
            m[r] = fmaxf(m[r], __shfl_xor_sync(0xffffffffu, m[r], o));
    }

    // ---- pass 2: sum of exp((t - m)/eps) ----
    float s[4] = {0.f, 0.f, 0.f, 0.f};
    float mb[4];
#pragma unroll
    for (int r = 0; r < 4; r++) mb[r] = -m[r] * C2;

#pragma unroll 2
    for (int j = lane; j < NP; j += 32) {
        float4 p = S[j];
#pragma unroll
        for (int r = 0; r < 4; r++) {
            float t = fmaf(rx[r], p.x, p.w);
            t = fmaf(ry[r], p.y, t);
            t = fmaf(rz[r], p.z, t);
            s[r] += ex2f(fmaf(t, C2, mb[r]));
        }
    }
#pragma unroll
    for (int r = 0; r < 4; r++) {
#pragma unroll
        for (int o = 16; o; o >>= 1)
            s[r] += __shfl_xor_sync(0xffffffffu, s[r], o);
    }

    if (lane == 0) {
#pragma unroll
        for (int r = 0; r < 4; r++) {
            float neww = EPSLOGMU - m[r] - EPS * (LN2 * lg2f(s[r]));
            reinterpret_cast<float*>(D + r)[3] = neww;  // write .w only
        }
    }
}

// ---------------------------------------------------------------------------
// Final: dist_i = N * sum_j exp((Aw_i + Bw_j + dot')/eps) * C_ij,
// partial[block] = sum over block's 32 rows of sqrt(dist + 1e-12).
// ---------------------------------------------------------------------------
__global__ __launch_bounds__(256) void dist_kernel() {
    __shared__ float sh[8];

    int lane = threadIdx.x & 31;
    int warp = threadIdx.x >> 5;
    int b    = blockIdx.y;
    int row0 = blockIdx.x * 32 + warp * 4;

    const float4* S = g_B + b * NP;
    const float4* D = g_A + b * NP + row0;

    float rx[4], ry[4], rz[4], nx[4], awc2[4];
#pragma unroll
    for (int r = 0; r < 4; r++) {
        float4 t = D[r];
        rx[r] = t.x; ry[r] = t.y; rz[r] = t.z;
        nx[r] = t.x * t.x + t.y * t.y + t.z * t.z;
        awc2[r] = t.w * C2;
    }

    float acc[4] = {0.f, 0.f, 0.f, 0.f};

#pragma unroll 2
    for (int j = lane; j < NP; j += 32) {
        float4 p = S[j];
        float h = 0.25f * (p.x * p.x + p.y * p.y + p.z * p.z);  // = |y_j|^2
        float zc = p.w * C2;
#pragma unroll
        for (int r = 0; r < 4; r++) {
            float d = rx[r] * p.x;
            d = fmaf(ry[r], p.y, d);
            d = fmaf(rz[r], p.z, d);                 // = 2*dot
            float e = ex2f(fmaf(d, C2, zc + awc2[r]));
            float Cc = (nx[r] + h) - d;              // C_ij
            acc[r] = fmaf(e, Cc, acc[r]);
        }
    }
#pragma unroll
    for (int r = 0; r < 4; r++) {
#pragma unroll
        for (int o = 16; o; o >>= 1)
            acc[r] += __shfl_xor_sync(0xffffffffu, acc[r], o);
    }

    if (lane == 0) {
        float local = 0.f;
#pragma unroll
        for (int r = 0; r < 4; r++)
            local += sqrtf(fmaf((float)NP, acc[r], 1e-12f));
        sh[warp] = local;
    }
    __syncthreads();
    if (threadIdx.x == 0) {
        float t = 0.f;
#pragma unroll
        for (int w = 0; w < 8; w++) t += sh[w];
        g_part[b * NBLK + blockIdx.x] = t;
    }
}

// Deterministic final reduction: 512 partials -> mean.
__global__ __launch_bounds__(512) void reduce_kernel(float* out) {
    __shared__ float sh[512];
    int t = threadIdx.x;
    sh[t] = g_part[t];
    __syncthreads();
    for (int o = 256; o; o >>= 1) {
        if (t < o) sh[t] += sh[t + o];
        __syncthreads();
    }
    if (t == 0) out[0] = sh[0] * (1.0f / (float)NTOT);
}

// ---------------------------------------------------------------------------
extern "C" void kernel_launch(void* const* d_in, const int* in_sizes, int n_in,
                              void* d_out, int out_size) {
    const float* p1 = (const float*)d_in[0];
    const float* p2 = (const float*)d_in[1];

    init_kernel<<<(2 * NTOT + 255) / 256, 256>>>(p1, p2);

    dim3 grid(NBLK, NB);
    for (int it = 0; it < ITERS; it++) {
        sink_kernel<0><<<grid, 256>>>();  // f from g
        sink_kernel<1><<<grid, 256>>>();  // g from new f
    }
    dist_kernel<<<grid, 256>>>();
    reduce_kernel<<<1, 512>>>((float*)d_out);
}

// round 7
// speedup vs baseline: 1.4931x; 1.4931x over previous
#include <cuda_runtime.h>

// EarthMoverDistance: entropic Sinkhorn OT, B=8, N=2048, D=3, eps=0.005, 50 iters.
//
// Packed layout (round-1 proven, NATURAL units -- precision critical!):
//   A[i] = (x0, x1, x2,  f_i - |x_i|^2)
//   B[j] = (2*y0, 2*y1, 2*y2,  g_j - |y_j|^2)
// Row update (DIR=0): t_j = Bw_j + x.(2y) = g_j - C_ij + |x_i|^2, all O(1).
// Stored dual: w_new = f_new - |x|^2 = EPSLOGMU - m - eps*ln(sum_j e^((t-m)/eps))
// (norm cancels). The *2 on the B side makes DIR=1 identical in form.
// The x C2 = log2(e)/eps scaling happens in ONE fma right before ex2, so fp32
// cancellation occurs at natural magnitudes (~1e-7 noise), not at ~1e3 where
// ulp is 2.4e-4 (the round-5 pre-scaled variant failed at rel_err 2e-3).
//
// Fast path (iters WARM..49): single sweep, shift = previous iteration's row
// max (exact for any shift; stale max moves <<0.28 natural units/iter, the
// clamp-80 window). New true max tracked in the same sweep.

#define NB      8
#define NP      2048
#define NTOT    (NB * NP)
#define ITERS   50
#define WARM    6                    // exact two-pass iterations
#define EPS     0.005f
#define LN2     0.69314718055994531f
#define C2      288.53900817779268f  // log2(e)/eps
#define EPSLOGMU (-0.038123094930796995f)  // -eps*ln(2048)
#define CLAMP   80.0f                // ex2 arg cap: 2048*2^80 << fp32 max
#define NBLK16  (NP / 16)            // 128 row-blocks (16 rows per CTA)
#define NBLK32  (NP / 32)
#define NPART   (NBLK32 * NB)

__device__ float4 g_A[NTOT];
__device__ float4 g_B[NTOT];
__device__ float  g_mA[NTOT];        // per-row shift (NATURAL units)
__device__ float  g_mB[NTOT];
__device__ float  g_part[NPART];

__device__ __forceinline__ float ex2f(float x) {
    float r; asm("ex2.approx.ftz.f32 %0, %1;" : "=f"(r) : "f"(x)); return r;
}
__device__ __forceinline__ float lg2f(float x) {
    float r; asm("lg2.approx.f32 %0, %1;" : "=f"(r) : "f"(x)); return r;
}

// ---------------------------------------------------------------------------
__global__ __launch_bounds__(256) void init_kernel(const float* __restrict__ p1,
                                                   const float* __restrict__ p2) {
    int idx = blockIdx.x * blockDim.x + threadIdx.x;
    if (idx < NTOT) {
        float x0 = p1[idx * 3], x1 = p1[idx * 3 + 1], x2 = p1[idx * 3 + 2];
        g_A[idx] = make_float4(x0, x1, x2, -(x0 * x0 + x1 * x1 + x2 * x2));
    } else if (idx < 2 * NTOT) {
        int k = idx - NTOT;
        float y0 = p2[k * 3], y1 = p2[k * 3 + 1], y2 = p2[k * 3 + 2];
        g_B[k] = make_float4(2.f * y0, 2.f * y1, 2.f * y2,
                             -(y0 * y0 + y1 * y1 + y2 * y2));
    }
}

// ---------------------------------------------------------------------------
// Exact two-pass half-step (warmup). CTA: 8 warps = 4 rowgroups x 2 j-halves.
// Stores the exact row max (natural units) for the fast kernels.
// ---------------------------------------------------------------------------
template <int DIR>
__global__ __launch_bounds__(256) void twopass_kernel() {
    const float4* __restrict__ src = (DIR == 0) ? g_B : g_A;
    float4*                    dst = (DIR == 0) ? g_A : g_B;
    float*                     mArr = (DIR == 0) ? g_mA : g_mB;

    __shared__ float sm_m[8][4];
    __shared__ float sm_s[8][4];

    int lane = threadIdx.x & 31;
    int warp = threadIdx.x >> 5;
    int rg   = warp >> 1;
    int half = warp & 1;
    int b    = blockIdx.y;
    int row0 = blockIdx.x * 16 + rg * 4;

    const float4* S = src + b * NP;
    float4*       D = dst + b * NP + row0;
    float*        M = mArr + b * NP + row0;

    float rx[4], ry[4], rz[4];
#pragma unroll
    for (int r = 0; r < 4; r++) {
        float4 t = D[r];
        rx[r] = t.x; ry[r] = t.y; rz[r] = t.z;
    }

    const float4* p = S + half * (NP / 2) + lane;

    // pass 1: max of t (natural units)
    float mx[4] = {-1e30f, -1e30f, -1e30f, -1e30f};
#pragma unroll 4
    for (int it = 0; it < NP / 64; it++) {
        float4 q = p[it * 32];
#pragma unroll
        for (int r = 0; r < 4; r++) {
            float t = fmaf(rx[r], q.x, q.w);
            t = fmaf(ry[r], q.y, t);
            t = fmaf(rz[r], q.z, t);
            mx[r] = fmaxf(mx[r], t);
        }
    }
#pragma unroll
    for (int r = 0; r < 4; r++)
#pragma unroll
        for (int o = 16; o; o >>= 1)
            mx[r] = fmaxf(mx[r], __shfl_xor_sync(0xffffffffu, mx[r], o));
    if (lane == 0) {
#pragma unroll
        for (int r = 0; r < 4; r++) sm_m[warp][r] = mx[r];
    }
    __syncthreads();

    float mt[4], mb[4];
#pragma unroll
    for (int r = 0; r < 4; r++) {
        mt[r] = fmaxf(sm_m[rg * 2][r], sm_m[rg * 2 + 1][r]);
        mb[r] = -mt[r] * C2;
    }

    // pass 2: sum of 2^(C2*t - C2*m); scaling folded into one fma so the
    // cancellation (t - m) effectively happens at natural magnitudes.
    float s[4] = {0.f, 0.f, 0.f, 0.f};
#pragma unroll 4
    for (int it = 0; it < NP / 64; it++) {
        float4 q = p[it * 32];
#pragma unroll
        for (int r = 0; r < 4; r++) {
            float t = fmaf(rx[r], q.x, q.w);
            t = fmaf(ry[r], q.y, t);
            t = fmaf(rz[r], q.z, t);
            s[r] += ex2f(fmaf(t, C2, mb[r]));
        }
    }
#pragma unroll
    for (int r = 0; r < 4; r++)
#pragma unroll
        for (int o = 16; o; o >>= 1)
            s[r] += __shfl_xor_sync(0xffffffffu, s[r], o);
    if (lane == 0) {
#pragma unroll
        for (int r = 0; r < 4; r++) sm_s[warp][r] = s[r];
    }
    __syncthreads();

    if (half == 0 && lane < 4) {
        int r = lane;
        float st = sm_s[warp][r] + sm_s[warp + 1][r];
        float w = EPSLOGMU - mt[r] - EPS * (LN2 * lg2f(st));
        reinterpret_cast<float*>(D + r)[3] = w;
        M[r] = mt[r];
    }
}

// ---------------------------------------------------------------------------
// Fast half-step: ONE sweep, shift = previous iteration's row max (natural
// units; exact identity for any shift). Tracks new true max in-sweep.
// ---------------------------------------------------------------------------
template <int DIR>
__global__ __launch_bounds__(256) void fast_kernel() {
    const float4* __restrict__ src = (DIR == 0) ? g_B : g_A;
    float4*                    dst = (DIR == 0) ? g_A : g_B;
    float*                     mArr = (DIR == 0) ? g_mA : g_mB;

    __shared__ float sm_m[8][4];
    __shared__ float sm_s[8][4];

    int lane = threadIdx.x & 31;
    int warp = threadIdx.x >> 5;
    int rg   = warp >> 1;
    int half = warp & 1;
    int b    = blockIdx.y;
    int row0 = blockIdx.x * 16 + rg * 4;

    const float4* S = src + b * NP;
    float4*       D = dst + b * NP + row0;
    float*        M = mArr + b * NP + row0;

    float rx[4], ry[4], rz[4], mloc[4], mb[4];
#pragma unroll
    for (int r = 0; r < 4; r++) {
        float4 t = D[r];
        rx[r] = t.x; ry[r] = t.y; rz[r] = t.z;
        mloc[r] = M[r];
        mb[r] = -mloc[r] * C2;
    }

    const float4* p = S + half * (NP / 2) + lane;

    float s[4] = {0.f, 0.f, 0.f, 0.f};
    float mx[4] = {-1e30f, -1e30f, -1e30f, -1e30f};
#pragma unroll 4
    for (int it = 0; it < NP / 64; it++) {
        float4 q = p[it * 32];
#pragma unroll
        for (int r = 0; r < 4; r++) {
            float t = fmaf(rx[r], q.x, q.w);
            t = fmaf(ry[r], q.y, t);
            t = fmaf(rz[r], q.z, t);
            mx[r] = fmaxf(mx[r], t);
            float a = fminf(fmaf(t, C2, mb[r]), CLAMP);  // overflow insurance
            s[r] += ex2f(a);
        }
    }
#pragma unroll
    for (int r = 0; r < 4; r++) {
#pragma unroll
        for (int o = 16; o; o >>= 1) {
            s[r]  += __shfl_xor_sync(0xffffffffu, s[r], o);
            mx[r]  = fmaxf(mx[r], __shfl_xor_sync(0xffffffffu, mx[r], o));
        }
    }
    if (lane == 0) {
#pragma unroll
        for (int r = 0; r < 4; r++) { sm_s[warp][r] = s[r]; sm_m[warp][r] = mx[r]; }
    }
    __syncthreads();

    if (half == 0 && lane < 4) {
        int r = lane;
        float st = sm_s[warp][r] + sm_s[warp + 1][r];
        float mt = fmaxf(sm_m[warp][r], sm_m[warp + 1][r]);
        float w = EPSLOGMU - mloc[r] - EPS * (LN2 * lg2f(st)); // shift used
        reinterpret_cast<float*>(D + r)[3] = w;
        M[r] = mt;                                              // fresh max
    }
}

// ---------------------------------------------------------------------------
// Final: dist_i = N * sum_j exp((w_i + w_j + dot')/eps * ln2-free) * C_ij.
// Exponent = C2*(Aw_i + Bw_j + 2x.y) = C2*(f+g-C); norms cancel. (Round-1
// proven form.)
// ---------------------------------------------------------------------------
__global__ __launch_bounds__(256) void dist_kernel() {
    __shared__ float sh[8];

    int lane = threadIdx.x & 31;
    int warp = threadIdx.x >> 5;
    int b    = blockIdx.y;
    int row0 = blockIdx.x * 32 + warp * 4;

    const float4* S = g_B + b * NP;
    const float4* D = g_A + b * NP + row0;

    float rx[4], ry[4], rz[4], nx[4], awc2[4];
#pragma unroll
    for (int r = 0; r < 4; r++) {
        float4 t = D[r];
        rx[r] = t.x; ry[r] = t.y; rz[r] = t.z;
        nx[r] = t.x * t.x + t.y * t.y + t.z * t.z;   // |x|^2
        awc2[r] = t.w * C2;
    }

    float acc[4] = {0.f, 0.f, 0.f, 0.f};

#pragma unroll 2
    for (int j = lane; j < NP; j += 32) {
        float4 q = S[j];
        float h = 0.25f * (q.x * q.x + q.y * q.y + q.z * q.z);  // |y_j|^2
        float zc = q.w * C2;
#pragma unroll
        for (int r = 0; r < 4; r++) {
            float d = rx[r] * q.x;
            d = fmaf(ry[r], q.y, d);
            d = fmaf(rz[r], q.z, d);                 // 2*x.y (natural)
            float e = ex2f(fmaf(d, C2, zc + awc2[r]));  // P_ij
            float Cc = (nx[r] + h) - d;              // C_ij
            acc[r] = fmaf(e, Cc, acc[r]);
        }
    }
#pragma unroll
    for (int r = 0; r < 4; r++)
#pragma unroll
        for (int o = 16; o; o >>= 1)
            acc[r] += __shfl_xor_sync(0xffffffffu, acc[r], o);

    if (lane == 0) {
        float local = 0.f;
#pragma unroll
        for (int r = 0; r < 4; r++)
            local += sqrtf(fmaf((float)NP, acc[r], 1e-12f));
        sh[warp] = local;
    }
    __syncthreads();
    if (threadIdx.x == 0) {
        float t = 0.f;
#pragma unroll
        for (int w = 0; w < 8; w++) t += sh[w];
        g_part[b * NBLK32 + blockIdx.x] = t;
    }
}

__global__ __launch_bounds__(512) void reduce_kernel(float* out) {
    __shared__ float sh[512];
    int t = threadIdx.x;
    sh[t] = g_part[t];
    __syncthreads();
    for (int o = 256; o; o >>= 1) {
        if (t < o) sh[t] += sh[t + o];
        __syncthreads();
    }
    if (t == 0) out[0] = sh[0] * (1.0f / (float)NTOT);
}

// ---------------------------------------------------------------------------
extern "C" void kernel_launch(void* const* d_in, const int* in_sizes, int n_in,
                              void* d_out, int out_size) {
    const float* p1 = (const float*)d_in[0];
    const float* p2 = (const float*)d_in[1];

    init_kernel<<<(2 * NTOT + 255) / 256, 256>>>(p1, p2);

    dim3 grid16(NBLK16, NB);
    for (int it = 0; it < WARM; it++) {
        twopass_kernel<0><<<grid16, 256>>>();
        twopass_kernel<1><<<grid16, 256>>>();
    }
    for (int it = WARM; it < ITERS; it++) {
        fast_kernel<0><<<grid16, 256>>>();
        fast_kernel<1><<<grid16, 256>>>();
    }

    dim3 grid32(NBLK32, NB);
    dist_kernel<<<grid32, 256>>>();
    reduce_kernel<<<1, 512>>>((float*)d_out);
}

// round 16
// speedup vs baseline: 1.5571x; 1.0429x over previous
#include <cuda_runtime.h>

// EarthMoverDistance: entropic Sinkhorn OT, B=8, N=2048, D=3, eps=0.005, 50 iters.
//
// Packed layout (NATURAL units -- precision critical, round-7 proven):
//   A[i] = (x0, x1, x2,  f_i - |x_i|^2)
//   B[j] = (2*y0, 2*y1, 2*y2,  g_j - |y_j|^2)
// Row update (DIR=0): t_j = Bw_j + x.(2y) = g_j - C_ij + |x_i|^2, all O(1).
// Stored dual: w_new = EPSLOGMU - lse  with lse = m + eps*ln(sum e^((t-m)/eps)).
// The xC2 (=log2(e)/eps) scaling happens in ONE fma right before ex2 so fp32
// cancellation occurs at natural magnitudes.
//
// Round-8 trick: the shift for the next sweep over the same row is derived
// from the dual itself: m' = EPSLOGMU - w_prev = previous lse, which is within
// eps*ln(N)=0.038 of the true row max -- far inside the +-0.3 stability window
// (clamp at 80 log2-units as insurance). No max tracking, no shift arrays.
// Epilogue becomes the fixpoint form  w_new = w_prev - eps*ln2*lg2(s).

#define NB      8
#define NP      2048
#define NTOT    (NB * NP)
#define ITERS   50
#define WARM    3                    // exact two-pass iterations
#define EPS     0.005f
#define LN2     0.69314718055994531f
#define C2      288.53900817779268f  // log2(e)/eps
#define EPSLOGMU (-0.038123094930796995f)  // -eps*ln(2048)
#define CLAMP   80.0f                // ex2 arg cap: 2048*2^80 << fp32 max
#define NBLK16  (NP / 16)            // 128 row-blocks (16 rows per CTA)
#define NBLK32  (NP / 32)
#define NPART   (NBLK32 * NB)

__device__ float4 g_A[NTOT];
__device__ float4 g_B[NTOT];
__device__ float  g_part[NPART];

__device__ __forceinline__ float ex2f(float x) {
    float r; asm("ex2.approx.ftz.f32 %0, %1;" : "=f"(r) : "f"(x)); return r;
}
__device__ __forceinline__ float lg2f(float x) {
    float r; asm("lg2.approx.f32 %0, %1;" : "=f"(r) : "f"(x)); return r;
}

// ---------------------------------------------------------------------------
__global__ __launch_bounds__(256) void init_kernel(const float* __restrict__ p1,
                                                   const float* __restrict__ p2) {
    int idx = blockIdx.x * blockDim.x + threadIdx.x;
    if (idx < NTOT) {
        float x0 = p1[idx * 3], x1 = p1[idx * 3 + 1], x2 = p1[idx * 3 + 2];
        g_A[idx] = make_float4(x0, x1, x2, -(x0 * x0 + x1 * x1 + x2 * x2));
    } else if (idx < 2 * NTOT) {
        int k = idx - NTOT;
        float y0 = p2[k * 3], y1 = p2[k * 3 + 1], y2 = p2[k * 3 + 2];
        g_B[k] = make_float4(2.f * y0, 2.f * y1, 2.f * y2,
                             -(y0 * y0 + y1 * y1 + y2 * y2));
    }
}

// ---------------------------------------------------------------------------
// Exact two-pass half-step (warmup). CTA: 8 warps = 4 rowgroups x 2 j-halves.
// After this, the stored dual encodes the exact lse => valid derived shift.
// ---------------------------------------------------------------------------
template <int DIR>
__global__ __launch_bounds__(256) void twopass_kernel() {
    const float4* __restrict__ src = (DIR == 0) ? g_B : g_A;
    float4*                    dst = (DIR == 0) ? g_A : g_B;

    __shared__ float sm_m[8][4];
    __shared__ float sm_s[8][4];

    int lane = threadIdx.x & 31;
    int warp = threadIdx.x >> 5;
    int rg   = warp >> 1;
    int half = warp & 1;
    int b    = blockIdx.y;
    int row0 = blockIdx.x * 16 + rg * 4;

    const float4* S = src + b * NP;
    float4*       D = dst + b * NP + row0;

    float rx[4], ry[4], rz[4];
#pragma unroll
    for (int r = 0; r < 4; r++) {
        float4 t = D[r];
        rx[r] = t.x; ry[r] = t.y; rz[r] = t.z;
    }

    const float4* p = S + half * (NP / 2) + lane;

    // pass 1: max of t (natural units)
    float mx[4] = {-1e30f, -1e30f, -1e30f, -1e30f};
#pragma unroll 4
    for (int it = 0; it < NP / 64; it++) {
        float4 q = p[it * 32];
#pragma unroll
        for (int r = 0; r < 4; r++) {
            float t = fmaf(rx[r], q.x, q.w);
            t = fmaf(ry[r], q.y, t);
            t = fmaf(rz[r], q.z, t);
            mx[r] = fmaxf(mx[r], t);
        }
    }
#pragma unroll
    for (int r = 0; r < 4; r++)
#pragma unroll
        for (int o = 16; o; o >>= 1)
            mx[r] = fmaxf(mx[r], __shfl_xor_sync(0xffffffffu, mx[r], o));
    if (lane == 0) {
#pragma unroll
        for (int r = 0; r < 4; r++) sm_m[warp][r] = mx[r];
    }
    __syncthreads();

    float mt[4], mb[4];
#pragma unroll
    for (int r = 0; r < 4; r++) {
        mt[r] = fmaxf(sm_m[rg * 2][r], sm_m[rg * 2 + 1][r]);
        mb[r] = -mt[r] * C2;
    }

    // pass 2: sum of 2^(C2*t - C2*m)
    float s[4] = {0.f, 0.f, 0.f, 0.f};
#pragma unroll 4
    for (int it = 0; it < NP / 64; it++) {
        float4 q = p[it * 32];
#pragma unroll
        for (int r = 0; r < 4; r++) {
            float t = fmaf(rx[r], q.x, q.w);
            t = fmaf(ry[r], q.y, t);
            t = fmaf(rz[r], q.z, t);
            s[r] += ex2f(fmaf(t, C2, mb[r]));
        }
    }
#pragma unroll
    for (int r = 0; r < 4; r++)
#pragma unroll
        for (int o = 16; o; o >>= 1)
            s[r] += __shfl_xor_sync(0xffffffffu, s[r], o);
    if (lane == 0) {
#pragma unroll
        for (int r = 0; r < 4; r++) sm_s[warp][r] = s[r];
    }
    __syncthreads();

    if (half == 0 && lane < 4) {
        int r = lane;
        float st = sm_s[warp][r] + sm_s[warp + 1][r];
        float w = EPSLOGMU - mt[r] - EPS * (LN2 * lg2f(st));
        reinterpret_cast<float*>(D + r)[3] = w;
    }
}

// ---------------------------------------------------------------------------
// Fast half-step: ONE sweep, shift derived from the row's own previous dual:
// m = EPSLOGMU - w_prev (= previous lse, within eps*lnN of the true max).
// No max tracking. Epilogue: w_new = w_prev - eps*ln2*lg2(s).
// ---------------------------------------------------------------------------
template <int DIR>
__global__ __launch_bounds__(256) void fast_kernel() {
    const float4* __restrict__ src = (DIR == 0) ? g_B : g_A;
    float4*                    dst = (DIR == 0) ? g_A : g_B;

    __shared__ float sm_s[8][4];

    int lane = threadIdx.x & 31;
    int warp = threadIdx.x >> 5;
    int rg   = warp >> 1;
    int half = warp & 1;
    int b    = blockIdx.y;
    int row0 = blockIdx.x * 16 + rg * 4;

    const float4* S = src + b * NP;
    float4*       D = dst + b * NP + row0;

    float rx[4], ry[4], rz[4], wprev[4], mb[4];
#pragma unroll
    for (int r = 0; r < 4; r++) {
        float4 t = D[r];
        rx[r] = t.x; ry[r] = t.y; rz[r] = t.z;
        wprev[r] = t.w;
        // -m*C2 with m = EPSLOGMU - w_prev
        mb[r] = (t.w - EPSLOGMU) * C2;
    }

    const float4* p = S + half * (NP / 2) + lane;

    float s[4] = {0.f, 0.f, 0.f, 0.f};
#pragma unroll 4
    for (int it = 0; it < NP / 64; it++) {
        float4 q = p[it * 32];
#pragma unroll
        for (int r = 0; r < 4; r++) {
            float t = fmaf(rx[r], q.x, q.w);
            t = fmaf(ry[r], q.y, t);
            t = fmaf(rz[r], q.z, t);
            float a = fminf(fmaf(t, C2, mb[r]), CLAMP);  // overflow insurance
            s[r] += ex2f(a);
        }
    }
#pragma unroll
    for (int r = 0; r < 4; r++)
#pragma unroll
        for (int o = 16; o; o >>= 1)
            s[r] += __shfl_xor_sync(0xffffffffu, s[r], o);
    if (lane == 0) {
#pragma unroll
        for (int r = 0; r < 4; r++) sm_s[warp][r] = s[r];
    }
    __syncthreads();

    if (half == 0 && lane < 4) {
        int r = lane;
        float st = sm_s[warp][r] + sm_s[warp + 1][r];
        float w = wprev[r] - EPS * (LN2 * lg2f(st));   // fixpoint form
        reinterpret_cast<float*>(D + r)[3] = w;
    }
}

// ---------------------------------------------------------------------------
// Final: dist_i = N * sum_j 2^(C2*(Aw_i + Bw_j + 2x.y)) * C_ij (norms cancel
// in the exponent); per-point sqrt, then global mean.
// ---------------------------------------------------------------------------
__global__ __launch_bounds__(256) void dist_kernel() {
    __shared__ float sh[8];

    int lane = threadIdx.x & 31;
    int warp = threadIdx.x >> 5;
    int b    = blockIdx.y;
    int row0 = blockIdx.x * 32 + warp * 4;

    const float4* S = g_B + b * NP;
    const float4* D = g_A + b * NP + row0;

    float rx[4], ry[4], rz[4], nx[4], awc2[4];
#pragma unroll
    for (int r = 0; r < 4; r++) {
        float4 t = D[r];
        rx[r] = t.x; ry[r] = t.y; rz[r] = t.z;
        nx[r] = t.x * t.x + t.y * t.y + t.z * t.z;   // |x|^2
        awc2[r] = t.w * C2;
    }

    float acc[4] = {0.f, 0.f, 0.f, 0.f};

#pragma unroll 2
    for (int j = lane; j < NP; j += 32) {
        float4 q = S[j];
        float h = 0.25f * (q.x * q.x + q.y * q.y + q.z * q.z);  // |y_j|^2
        float zc = q.w * C2;
#pragma unroll
        for (int r = 0; r < 4; r++) {
            float d = rx[r] * q.x;
            d = fmaf(ry[r], q.y, d);
            d = fmaf(rz[r], q.z, d);                 // 2*x.y (natural)
            float e = ex2f(fmaf(d, C2, zc + awc2[r]));  // P_ij
            float Cc = (nx[r] + h) - d;              // C_ij
            acc[r] = fmaf(e, Cc, acc[r]);
        }
    }
#pragma unroll
    for (int r = 0; r < 4; r++)
#pragma unroll
        for (int o = 16; o; o >>= 1)
            acc[r] += __shfl_xor_sync(0xffffffffu, acc[r], o);

    if (lane == 0) {
        float local = 0.f;
#pragma unroll
        for (int r = 0; r < 4; r++)
            local += sqrtf(fmaf((float)NP, acc[r], 1e-12f));
        sh[warp] = local;
    }
    __syncthreads();
    if (threadIdx.x == 0) {
        float t = 0.f;
#pragma unroll
        for (int w = 0; w < 8; w++) t += sh[w];
        g_part[b * NBLK32 + blockIdx.x] = t;
    }
}

__global__ __launch_bounds__(512) void reduce_kernel(float* out) {
    __shared__ float sh[512];
    int t = threadIdx.x;
    sh[t] = g_part[t];
    __syncthreads();
    for (int o = 256; o; o >>= 1) {
        if (t < o) sh[t] += sh[t + o];
        __syncthreads();
    }
    if (t == 0) out[0] = sh[0] * (1.0f / (float)NTOT);
}

// ---------------------------------------------------------------------------
extern "C" void kernel_launch(void* const* d_in, const int* in_sizes, int n_in,
                              void* d_out, int out_size) {
    const float* p1 = (const float*)d_in[0];
    const float* p2 = (const float*)d_in[1];

    init_kernel<<<(2 * NTOT + 255) / 256, 256>>>(p1, p2);

    dim3 grid16(NBLK16, NB);
    for (int it = 0; it < WARM; it++) {
        twopass_kernel<0><<<grid16, 256>>>();
        twopass_kernel<1><<<grid16, 256>>>();
    }
    for (int it = WARM; it < ITERS; it++) {
        fast_kernel<0><<<grid16, 256>>>();
        fast_kernel<1><<<grid16, 256>>>();
    }

    dim3 grid32(NBLK32, NB);
    dist_kernel<<<grid32, 256>>>();
    reduce_kernel<<<1, 512>>>((float*)d_out);
}